// round 2
// baseline (speedup 1.0000x reference)
#include <cuda_runtime.h>
#include <cuda_bf16.h>

#define FULL_MASK 0xFFFFFFFFu

constexpr int E_EDGES = 65536;
constexpr int F_DIM   = 128;
constexpr int D_DEG   = 32;

// One warp per TWO consecutive edges (2w, 2w+1); one-shot, no grid-stride loop.
//   lane l owns feature channels [4l, 4l+4) as a float4, and neighbor slot l.
// out[e] = sum_f xi[f]*xj[f]*W[f] + sum_{d: ni[d] in nj} dot(x[ni[d]], W[F:2F]) + b
__global__ void __launch_bounds__(256)
ncn_kernel(const float* __restrict__ x,
           const int*   __restrict__ nbr,
           const int*   __restrict__ tar_ei,
           const float* __restrict__ W,
           const float* __restrict__ b,
           float*       __restrict__ out)
{
    const int lane = threadIdx.x & 31;
    const int w    = (blockIdx.x * blockDim.x + threadIdx.x) >> 5;   // warp id = edge pair id
    const int e0   = 2 * w;                                          // e0 < E, e0+1 < E

    // Edge-pair indices: coalesced int2 loads (tar_ei is [2, E] row-major)
    const int2 ii = *reinterpret_cast<const int2*>(tar_ei + e0);            // sources
    const int2 jj = *reinterpret_cast<const int2*>(tar_ei + E_EDGES + e0);  // dests

    // Front-batch ALL heavy loads: 4 x-rows (512B each, warp-coalesced) + 4 nbr entries.
    const float4* xv = reinterpret_cast<const float4*>(x);
    const float4 a0 = __ldg(&xv[(size_t)ii.x * (F_DIM/4) + lane]);
    const float4 c0 = __ldg(&xv[(size_t)jj.x * (F_DIM/4) + lane]);
    const float4 a1 = __ldg(&xv[(size_t)ii.y * (F_DIM/4) + lane]);
    const float4 c1 = __ldg(&xv[(size_t)jj.y * (F_DIM/4) + lane]);

    const int ni0 = __ldg(nbr + (size_t)ii.x * D_DEG + lane);
    const int nj0 = __ldg(nbr + (size_t)jj.x * D_DEG + lane);
    const int ni1 = __ldg(nbr + (size_t)ii.y * D_DEG + lane);
    const int nj1 = __ldg(nbr + (size_t)jj.y * D_DEG + lane);

    // Per-lane weight slices (W is [256,1]): W0 = W[0:128], W1 = W[128:256]
    const float4 w0 = __ldg(&reinterpret_cast<const float4*>(W)[lane]);
    const float4 w1 = __ldg(&reinterpret_cast<const float4*>(W + F_DIM)[lane]);
    const float  bv = __ldg(b);

    // (xi * xj) . W0 partials for both edges
    float acc0 = a0.x*c0.x*w0.x + a0.y*c0.y*w0.y + a0.z*c0.z*w0.z + a0.w*c0.w*w0.w;
    float acc1 = a1.x*c1.x*w0.x + a1.y*c1.y*w0.y + a1.z*c1.z*w0.z + a1.w*c1.w*w0.w;

    // Interleaved lower_bound binary searches of ni in sorted distributed nj
    // (clip to D-1 + equality, matching jnp.searchsorted semantics).
    int lo0 = 0, hi0 = D_DEG - 1;
    int lo1 = 0, hi1 = D_DEG - 1;
    #pragma unroll
    for (int s = 0; s < 5; ++s) {
        const int m0 = (lo0 + hi0) >> 1;
        const int m1 = (lo1 + hi1) >> 1;
        const int v0 = __shfl_sync(FULL_MASK, nj0, m0);
        const int v1 = __shfl_sync(FULL_MASK, nj1, m1);
        if (v0 < ni0) lo0 = m0 + 1; else hi0 = m0;
        if (v1 < ni1) lo1 = m1 + 1; else hi1 = m1;
    }
    const bool hit0 = (__shfl_sync(FULL_MASK, nj0, lo0) == ni0);
    const bool hit1 = (__shfl_sync(FULL_MASK, nj1, lo1) == ni1);

    // Rare common-neighbor contributions (warp-uniform masks keep convergence).
    unsigned hm0 = __ballot_sync(FULL_MASK, hit0);
    while (hm0) {
        const int h = __ffs(hm0) - 1; hm0 &= hm0 - 1u;
        const int cn = __shfl_sync(FULL_MASK, ni0, h);
        const float4 xc = __ldg(&xv[(size_t)cn * (F_DIM/4) + lane]);
        acc0 += xc.x*w1.x + xc.y*w1.y + xc.z*w1.z + xc.w*w1.w;
    }
    unsigned hm1 = __ballot_sync(FULL_MASK, hit1);
    while (hm1) {
        const int h = __ffs(hm1) - 1; hm1 &= hm1 - 1u;
        const int cn = __shfl_sync(FULL_MASK, ni1, h);
        const float4 xc = __ldg(&xv[(size_t)cn * (F_DIM/4) + lane]);
        acc1 += xc.x*w1.x + xc.y*w1.y + xc.z*w1.z + xc.w*w1.w;
    }

    // Interleaved warp reductions
    #pragma unroll
    for (int off = 16; off >= 1; off >>= 1) {
        acc0 += __shfl_down_sync(FULL_MASK, acc0, off);
        acc1 += __shfl_down_sync(FULL_MASK, acc1, off);
    }

    if (lane == 0) {
        float2 r; r.x = acc0 + bv; r.y = acc1 + bv;
        *reinterpret_cast<float2*>(out + e0) = r;   // coalesced 8B store
    }
}

extern "C" void kernel_launch(void* const* d_in, const int* in_sizes, int n_in,
                              void* d_out, int out_size)
{
    const float* x      = (const float*)d_in[0];
    const int*   nbr    = (const int*)  d_in[1];
    const int*   tar_ei = (const int*)  d_in[2];
    const float* W      = (const float*)d_in[3];
    const float* b      = (const float*)d_in[4];
    float*       out    = (float*)d_out;

    // 32768 warps, one edge pair each: 4096 blocks x 256 threads, single shot.
    ncn_kernel<<<4096, 256>>>(x, nbr, tar_ei, W, b, out);
}